// round 2
// baseline (speedup 1.0000x reference)
#include <cuda_runtime.h>

// NablaT 3D: out[z,y,x] = bdiff_z(x0) + bdiff_y(x1) + bdiff_x(x2)
// bdiff along dim d: out[i] = a - b, a = (i>0)? v[i-1] : 0, b = (i<S-1)? v[i] : 0
//
// x: [3, 320, 320, 320] fp32. out: [320,320,320] fp32.
// Each thread: 4 x-contiguous outputs (float4) x 4 consecutive z-planes.
// z-unroll lets the 5 x0-plane loads serve 4 outputs (register reuse) and
// front-batches ~21 independent LDGs per thread for max MLP.

#define S 320
#define PLANE (S * S)           // 102400
#define VOL   (S * S * S)      // 32768000
#define X4    (S / 4)          // 80
#define P4    (PLANE / 4)      // 25600

__global__ __launch_bounds__(320)
void nablat_kernel(const float* __restrict__ xin, float* __restrict__ out) {
    const int x4    = threadIdx.x;                          // 0..79
    const int y     = blockIdx.y * 4 + threadIdx.y;         // 0..319
    const int zbase = blockIdx.z * 4;                       // 0,4,...,316
    const int xi    = x4 * 4;

    const long r4 = ((long)y * S + xi) >> 2;  // float4 index within a plane

    const float4* __restrict__ p0 = (const float4*)(xin);
    const float4* __restrict__ p1 = (const float4*)(xin + (long)VOL);
    const float4* __restrict__ p2 = (const float4*)(xin + 2L * VOL);
    const float*  __restrict__ s2 = xin + 2L * VOL;

    const float4 zero = make_float4(0.f, 0.f, 0.f, 0.f);

    // ---- x0 (z axis): planes zbase-1 .. zbase+3 (5 loads, 4 outputs) ----
    // a0(z) = v0[k], b0(z) = v0[k+1] for z = zbase+k.
    // v0[0] zero iff z==0 boundary (zbase==0); v0[4] zero iff z==S-1 (zbase==316).
    float4 v0[5];
    {
        const long pb = (long)(zbase - 1) * P4 + r4;
        v0[0] = (zbase > 0) ? __ldg(&p0[pb])          : zero;
        v0[1] = __ldg(&p0[pb + 1 * P4]);
        v0[2] = __ldg(&p0[pb + 2 * P4]);
        v0[3] = __ldg(&p0[pb + 3 * P4]);
        v0[4] = (zbase + 3 < S - 1) ? __ldg(&p0[pb + 4 * P4]) : zero;
    }

    // ---- x1 (y axis): b1 = x1[z,y], a1 = x1[z,y-1] ----
    float4 b1[4], a1[4];
    const bool y_lo = (y > 0);
    const bool y_hi = (y < S - 1);
    #pragma unroll
    for (int k = 0; k < 4; k++) {
        const long idx = (long)(zbase + k) * P4 + r4;
        b1[k] = y_hi ? __ldg(&p1[idx])          : zero;
        a1[k] = y_lo ? __ldg(&p1[idx - S / 4])  : zero;
    }

    // ---- x2 (x axis): row vector + left-halo scalar ----
    float4 v2[4];
    float  prev[4];
    const bool x_lo = (xi > 0);
    #pragma unroll
    for (int k = 0; k < 4; k++) {
        const long idx = (long)(zbase + k) * P4 + r4;
        v2[k]   = __ldg(&p2[idx]);
        prev[k] = x_lo ? __ldg(&s2[idx * 4 - 1]) : 0.f;
    }

    // ---- combine + streaming store ----
    const bool lastx = (x4 == X4 - 1);
    #pragma unroll
    for (int k = 0; k < 4; k++) {
        const float b2w = lastx ? 0.f : v2[k].w;
        float4 o;
        o.x = (v0[k].x - v0[k + 1].x) + (a1[k].x - b1[k].x) + (prev[k] - v2[k].x);
        o.y = (v0[k].y - v0[k + 1].y) + (a1[k].y - b1[k].y) + (v2[k].x - v2[k].y);
        o.z = (v0[k].z - v0[k + 1].z) + (a1[k].z - b1[k].z) + (v2[k].y - v2[k].z);
        o.w = (v0[k].w - v0[k + 1].w) + (a1[k].w - b1[k].w) + (v2[k].z - b2w);
        __stcs(&((float4*)out)[(long)(zbase + k) * P4 + r4], o);
    }
}

extern "C" void kernel_launch(void* const* d_in, const int* in_sizes, int n_in,
                              void* d_out, int out_size) {
    const float* x = (const float*)d_in[0];
    float* out = (float*)d_out;

    dim3 block(X4, 4, 1);        // 320 threads
    dim3 grid(1, S / 4, S / 4);  // (1, 80, 80)
    nablat_kernel<<<grid, block>>>(x, out);
}

// round 3
// speedup vs baseline: 1.0806x; 1.0806x over previous
#include <cuda_runtime.h>

// NablaT 3D: out[z,y,x] = bdiff_z(x0) + bdiff_y(x1) + bdiff_x(x2)
// bdiff along dim d: out[i] = a - b, a = (i>0)? v[i-1] : 0, b = (i<S-1)? v[i] : 0
//
// x: [3, 320, 320, 320] fp32. out: [320,320,320] fp32.
// One thread per float4 of output, flat 256-thread blocks for 100% occupancy.

#define S 320
#define PLANE (S * S)           // 102400
#define VOL   (S * S * S)       // 32768000
#define X4    (S / 4)           // 80
#define P4    (PLANE / 4)       // 25600
#define NV4   (VOL / 4)         // 8192000 float4 outputs

__global__ __launch_bounds__(256)
void nablat_kernel(const float* __restrict__ xin, float* __restrict__ out) {
    const unsigned t = blockIdx.x * 256u + threadIdx.x;  // flat float4 index == [z,y,x4]
    if (t >= NV4) return;

    const unsigned x4  = t % X4;
    const unsigned rem = t / X4;
    const unsigned y   = rem % S;
    const unsigned z   = rem / S;
    const unsigned xi  = x4 * 4;

    const float4* __restrict__ p0 = (const float4*)(xin);
    const float4* __restrict__ p1 = (const float4*)(xin + (long)VOL);
    const float4* __restrict__ p2 = (const float4*)(xin + 2L * VOL);
    const float*  __restrict__ s2 = xin + 2L * VOL;

    const float4 zero = make_float4(0.f, 0.f, 0.f, 0.f);

    // axis 0 (z): a0 = x0[z-1], b0 = x0[z] (b zeroed at z==S-1)
    float4 b0 = (z < S - 1) ? __ldg(&p0[t])      : zero;
    float4 a0 = (z > 0)     ? __ldg(&p0[t - P4]) : zero;

    // axis 1 (y): a1 = x1[y-1], b1 = x1[y]
    float4 b1 = (y < S - 1) ? __ldg(&p1[t])        : zero;
    float4 a1 = (y > 0)     ? __ldg(&p1[t - X4])   : zero;

    // axis 2 (x): within-vector shift; left-halo scalar at xi-1
    float4 v2   = __ldg(&p2[t]);
    float  prev = (xi > 0) ? __ldg(&s2[(long)t * 4 - 1]) : 0.f;
    float  b2w  = (x4 == X4 - 1) ? 0.f : v2.w;   // x == S-1 boundary

    float4 o;
    o.x = (a0.x - b0.x) + (a1.x - b1.x) + (prev - v2.x);
    o.y = (a0.y - b0.y) + (a1.y - b1.y) + (v2.x - v2.y);
    o.z = (a0.z - b0.z) + (a1.z - b1.z) + (v2.y - v2.z);
    o.w = (a0.w - b0.w) + (a1.w - b1.w) + (v2.z - b2w);

    ((float4*)out)[t] = o;
}

extern "C" void kernel_launch(void* const* d_in, const int* in_sizes, int n_in,
                              void* d_out, int out_size) {
    const float* x = (const float*)d_in[0];
    float* out = (float*)d_out;

    nablat_kernel<<<NV4 / 256, 256>>>(x, out);   // 32000 blocks, exact fit
}